// round 5
// baseline (speedup 1.0000x reference)
#include <cuda_runtime.h>
#include <math.h>

// Problem constants
#define Bn 256
#define Dn 10
#define Mn 32
#define Pn 36
#define In 8
#define On 16

#define THREADS 160            // 5 warps; warp w handles d=w and d=w+5; lane = m

// x smem row stride (P*I=288 + 4 pad) -> conflict-free LDS.128
#define XROW 292
#define XS_FLOATS (Mn * XROW)           // 9344
#define WVS_FLOATS (Dn * Mn * In)       // 2560
#define CSROW 37                        // float2 row stride for stats (pad)
#define CS_FLOAT2S (Mn * CSROW)         // 1184
#define SMEM_FLOATS (XS_FLOATS + WVS_FLOATS + 2 * CS_FLOAT2S)   // 14272 -> 57088 B

// Transposed W: Wt[d][o][ih][m] as float4 -> coalesced LDG.128 over lane m
__device__ float4 Wt_g[Dn * On * 2 * Mn];

__global__ void transpose_W_kernel(const float* __restrict__ W) {
    int idx = blockIdx.x * blockDim.x + threadIdx.x;
    if (idx >= Dn * On * 2 * Mn) return;
    int m  = idx & 31;
    int r  = idx >> 5;
    int ih = r & 1;  r >>= 1;
    int o  = r & 15;
    int d  = r >> 4;
    const float4* Wsrc = (const float4*)W;
    Wt_g[idx] = Wsrc[((d * Mn + m) * On + o) * 2 + ih];
}

// Dual-stream distributed compute_v: two independent d's per warp, interleaved.
// Returns vd[s] = squash(s_d)[o] on lanes 2o, 2o+1 (o = m>>1).
__device__ __forceinline__ void compute_v2(int d0, int d1, int m,
                                           const float xc0[In], const float xc1[In],
                                           float vd[2]) {
    const float4* W0 = Wt_g + (d0 * On * 2) * Mn + m;
    const float4* W1 = Wt_g + (d1 * On * 2) * Mn + m;
    float v[2][On];
#pragma unroll
    for (int o = 0; o < On; o++) {
        float4 a0 = __ldg(W0 + (2 * o) * Mn);
        float4 b0 = __ldg(W0 + (2 * o + 1) * Mn);
        float4 a1 = __ldg(W1 + (2 * o) * Mn);
        float4 b1 = __ldg(W1 + (2 * o + 1) * Mn);
        v[0][o] = a0.x * xc0[0] + a0.y * xc0[1] + a0.z * xc0[2] + a0.w * xc0[3]
                + b0.x * xc0[4] + b0.y * xc0[5] + b0.z * xc0[6] + b0.w * xc0[7];
        v[1][o] = a1.x * xc1[0] + a1.y * xc1[1] + a1.z * xc1[2] + a1.w * xc1[3]
                + b1.x * xc1[4] + b1.y * xc1[5] + b1.z * xc1[6] + b1.w * xc1[7];
    }
    bool h = (m & 16);
    float a8[2][8];
#pragma unroll
    for (int s = 0; s < 2; s++)
#pragma unroll
        for (int j = 0; j < 8; j++) {
            float send = h ? v[s][j] : v[s][j + 8];
            float keep = h ? v[s][j + 8] : v[s][j];
            a8[s][j] = keep + __shfl_xor_sync(0xffffffffu, send, 16);
        }
    h = (m & 8);
    float a4[2][4];
#pragma unroll
    for (int s = 0; s < 2; s++)
#pragma unroll
        for (int j = 0; j < 4; j++) {
            float send = h ? a8[s][j] : a8[s][j + 4];
            float keep = h ? a8[s][j + 4] : a8[s][j];
            a4[s][j] = keep + __shfl_xor_sync(0xffffffffu, send, 8);
        }
    h = (m & 4);
    float a2[2][2];
#pragma unroll
    for (int s = 0; s < 2; s++)
#pragma unroll
        for (int j = 0; j < 2; j++) {
            float send = h ? a4[s][j] : a4[s][j + 2];
            float keep = h ? a4[s][j + 2] : a4[s][j];
            a2[s][j] = keep + __shfl_xor_sync(0xffffffffu, send, 4);
        }
    h = (m & 2);
    float s1[2];
#pragma unroll
    for (int s = 0; s < 2; s++) {
        float send = h ? a2[s][0] : a2[s][1];
        float keep = h ? a2[s][1] : a2[s][0];
        s1[s] = keep + __shfl_xor_sync(0xffffffffu, send, 2);
        s1[s] += __shfl_xor_sync(0xffffffffu, s1[s], 1);
    }
    // squash (sum of squares over the 16 distinct o via bit0-coset butterfly)
#pragma unroll
    for (int s = 0; s < 2; s++) {
        float sq = s1[s] * s1[s];
        sq += __shfl_xor_sync(0xffffffffu, sq, 2);
        sq += __shfl_xor_sync(0xffffffffu, sq, 4);
        sq += __shfl_xor_sync(0xffffffffu, sq, 8);
        sq += __shfl_xor_sync(0xffffffffu, sq, 16);
        float k = __fdividef(sq, 1.0f + sq) * rsqrtf(sq + 1e-7f);
        vd[s] = s1[s] * k;
    }
}

__device__ __forceinline__ void bcast_v2(const float vd[2], float vo[2][On]) {
#pragma unroll
    for (int o = 0; o < On; o++) {
        vo[0][o] = __shfl_sync(0xffffffffu, vd[0], 2 * o);
        vo[1][o] = __shfl_sync(0xffffffffu, vd[1], 2 * o);
    }
}

__device__ __forceinline__ void compute_wv2(int d0, int d1, int m,
                                            const float vo[2][On], float wv[2][In]) {
    const float4* W0 = Wt_g + (d0 * On * 2) * Mn + m;
    const float4* W1 = Wt_g + (d1 * On * 2) * Mn + m;
#pragma unroll
    for (int s = 0; s < 2; s++)
#pragma unroll
        for (int i = 0; i < In; i++) wv[s][i] = 0.f;
#pragma unroll
    for (int o = 0; o < On; o++) {
        float4 a0 = __ldg(W0 + (2 * o) * Mn);
        float4 b0 = __ldg(W0 + (2 * o + 1) * Mn);
        float4 a1 = __ldg(W1 + (2 * o) * Mn);
        float4 b1 = __ldg(W1 + (2 * o + 1) * Mn);
        float v0 = vo[0][o], v1 = vo[1][o];
        wv[0][0] += a0.x * v0; wv[0][1] += a0.y * v0; wv[0][2] += a0.z * v0; wv[0][3] += a0.w * v0;
        wv[0][4] += b0.x * v0; wv[0][5] += b0.y * v0; wv[0][6] += b0.z * v0; wv[0][7] += b0.w * v0;
        wv[1][0] += a1.x * v1; wv[1][1] += a1.y * v1; wv[1][2] += a1.z * v1; wv[1][3] += a1.w * v1;
        wv[1][4] += b1.x * v1; wv[1][5] += b1.y * v1; wv[1][6] += b1.z * v1; wv[1][7] += b1.w * v1;
    }
}

__device__ __forceinline__ float dot8(const float4 a, const float4 q, const float w[In]) {
    return a.x * w[0] + a.y * w[1] + a.z * w[2] + a.w * w[3]
         + q.x * w[4] + q.y * w[5] + q.z * w[6] + q.w * w[7];
}

__global__ __launch_bounds__(THREADS, 2)
void caps_routing_kernel(const float* __restrict__ x,
                         float* __restrict__ out) {
    extern __shared__ float sm[];
    float*  xs   = sm;                          // [Mn][XROW]
    float*  wvs  = xs + XS_FLOATS;              // [Dn*Mn][8]
    float2* cs   = (float2*)(wvs + WVS_FLOATS); // [Mn][CSROW] (mx, rs)
    float*  xsum = (float*)cs;                  // early overlap: [Mn][9]

    const int bidx = blockIdx.x;
    const int tid  = threadIdx.x;
    const int w    = tid >> 5;            // 0..4
    const int m    = tid & 31;
    const int d0   = w, d1 = w + 5;

    // ---- load x[bidx] into padded smem (coalesced float4) ----
    {
        const float4* xg = (const float4*)(x + (size_t)bidx * (Mn * Pn * In));
        const int row4 = (Pn * In) / 4;   // 72
        for (int idx = tid; idx < Mn * row4; idx += THREADS) {
            int mm = idx / row4;
            int j  = idx - mm * row4;
            ((float4*)(xs + mm * XROW))[j] = xg[idx];
        }
    }
    __syncthreads();

    // ---- cooperative xsum[m][i] = (1/D) * sum_p x[m,p,i] ----
    for (int t = tid; t < Mn * In; t += THREADS) {
        int mm = t >> 3, ii = t & 7;
        const float* xr = xs + mm * XROW + ii;
        float s = 0.f;
#pragma unroll
        for (int p = 0; p < Pn; p++) s += xr[8 * p];
        xsum[mm * 9 + ii] = s * (1.0f / Dn);
    }
    __syncthreads();

    const float4* xm = (const float4*)(xs + m * XROW);

    float xc0[In], xc1[In], vd[2], vo[2][On], wv1[2][In], wv2[2][In];

    // ================= iteration 1: c = 1/D (xc same for both d) =================
#pragma unroll
    for (int i = 0; i < In; i++) { xc0[i] = xsum[m * 9 + i]; xc1[i] = xc0[i]; }

    compute_v2(d0, d1, m, xc0, xc1, vd);
    bcast_v2(vd, vo);
    compute_wv2(d0, d1, m, vo, wv1);

    // publish wv1 for cross-d softmax stats
    {
        float4* w40 = (float4*)(wvs + (d0 * Mn + m) * In);
        w40[0] = make_float4(wv1[0][0], wv1[0][1], wv1[0][2], wv1[0][3]);
        w40[1] = make_float4(wv1[0][4], wv1[0][5], wv1[0][6], wv1[0][7]);
        float4* w41 = (float4*)(wvs + (d1 * Mn + m) * In);
        w41[0] = make_float4(wv1[1][0], wv1[1][1], wv1[1][2], wv1[1][3]);
        w41[1] = make_float4(wv1[1][4], wv1[1][5], wv1[1][6], wv1[1][7]);
    }
    __syncthreads();

    // ===== axis-1 (d) softmax stats per (m,p): b[d] = x_p . wv1[d,m] =====
    for (int col = tid; col < Mn * Pn; col += THREADS) {
        int cm = col / Pn, cp = col - cm * Pn;
        float4 xa = *(const float4*)(xs + cm * XROW + 8 * cp);
        float4 xq = *(const float4*)(xs + cm * XROW + 8 * cp + 4);
        float bv[Dn];
        float vmax = -1e30f;
#pragma unroll
        for (int dd = 0; dd < Dn; dd++) {
            const float4* w4 = (const float4*)(wvs + (dd * Mn + cm) * In);
            float4 wa = w4[0], wb = w4[1];
            float b = xa.x * wa.x + xa.y * wa.y + xa.z * wa.z + xa.w * wa.w
                    + xq.x * wb.x + xq.y * wb.y + xq.z * wb.z + xq.w * wb.w;
            bv[dd] = b;
            vmax = fmaxf(vmax, b);
        }
        float ssum = 0.f;
#pragma unroll
        for (int dd = 0; dd < Dn; dd++) ssum += __expf(bv[dd] - vmax);
        cs[cm * CSROW + cp] = make_float2(vmax, __fdividef(1.0f, ssum));
    }
    __syncthreads();

    // ======= iteration 2: one x pass feeds BOTH d streams =======
    {
        const float2* csr = cs + m * CSROW;
#pragma unroll
        for (int i = 0; i < In; i++) { xc0[i] = 0.f; xc1[i] = 0.f; }
        for (int p = 0; p < Pn; p++) {
            float4 a = xm[2 * p], q = xm[2 * p + 1];
            float2 st = csr[p];
            float c0 = __expf(dot8(a, q, wv1[0]) - st.x) * st.y;
            float c1 = __expf(dot8(a, q, wv1[1]) - st.x) * st.y;
            xc0[0] += c0 * a.x; xc0[1] += c0 * a.y; xc0[2] += c0 * a.z; xc0[3] += c0 * a.w;
            xc0[4] += c0 * q.x; xc0[5] += c0 * q.y; xc0[6] += c0 * q.z; xc0[7] += c0 * q.w;
            xc1[0] += c1 * a.x; xc1[1] += c1 * a.y; xc1[2] += c1 * a.z; xc1[3] += c1 * a.w;
            xc1[4] += c1 * q.x; xc1[5] += c1 * q.y; xc1[6] += c1 * q.z; xc1[7] += c1 * q.w;
        }
    }
    compute_v2(d0, d1, m, xc0, xc1, vd);
    bcast_v2(vd, vo);
    compute_wv2(d0, d1, m, vo, wv2);

    // b_final(p) = x_p . (wv1 + wv2)
    float wvt0[In], wvt1[In];
#pragma unroll
    for (int i = 0; i < In; i++) {
        wvt0[i] = wv1[0][i] + wv2[0][i];
        wvt1[i] = wv1[1][i] + wv2[1][i];
    }

    // ===== FUSED final: axis-3 softmax (online) + weighted x acc, both d's =====
    {
        float M0 = -1e30f, Z0 = 0.f, M1 = -1e30f, Z1 = 0.f;
        float acc0[In], acc1[In];
#pragma unroll
        for (int i = 0; i < In; i++) { acc0[i] = 0.f; acc1[i] = 0.f; }
        for (int p = 0; p < Pn; p++) {
            float4 a = xm[2 * p], q = xm[2 * p + 1];
            float b0 = dot8(a, q, wvt0);
            float b1 = dot8(a, q, wvt1);
            float M0n = fmaxf(M0, b0);
            float M1n = fmaxf(M1, b1);
            float sc0 = __expf(M0 - M0n), w0 = __expf(b0 - M0n);
            float sc1 = __expf(M1 - M1n), w1 = __expf(b1 - M1n);
            Z0 = Z0 * sc0 + w0;  Z1 = Z1 * sc1 + w1;
            acc0[0] = acc0[0] * sc0 + w0 * a.x;  acc1[0] = acc1[0] * sc1 + w1 * a.x;
            acc0[1] = acc0[1] * sc0 + w0 * a.y;  acc1[1] = acc1[1] * sc1 + w1 * a.y;
            acc0[2] = acc0[2] * sc0 + w0 * a.z;  acc1[2] = acc1[2] * sc1 + w1 * a.z;
            acc0[3] = acc0[3] * sc0 + w0 * a.w;  acc1[3] = acc1[3] * sc1 + w1 * a.w;
            acc0[4] = acc0[4] * sc0 + w0 * q.x;  acc1[4] = acc1[4] * sc1 + w1 * q.x;
            acc0[5] = acc0[5] * sc0 + w0 * q.y;  acc1[5] = acc1[5] * sc1 + w1 * q.y;
            acc0[6] = acc0[6] * sc0 + w0 * q.z;  acc1[6] = acc1[6] * sc1 + w1 * q.z;
            acc0[7] = acc0[7] * sc0 + w0 * q.w;  acc1[7] = acc1[7] * sc1 + w1 * q.w;
            M0 = M0n; M1 = M1n;
        }
        float rz0 = __fdividef(1.0f, Z0);
        float rz1 = __fdividef(1.0f, Z1);
#pragma unroll
        for (int i = 0; i < In; i++) { xc0[i] = acc0[i] * rz0; xc1[i] = acc1[i] * rz1; }
    }
    compute_v2(d0, d1, m, xc0, xc1, vd);

    if (!(m & 1)) {
        out[((size_t)bidx * Dn + d0) * On + (m >> 1)] = vd[0];
        out[((size_t)bidx * Dn + d1) * On + (m >> 1)] = vd[1];
    }
}

extern "C" void kernel_launch(void* const* d_in, const int* in_sizes, int n_in,
                              void* d_out, int out_size) {
    const float* x = (const float*)d_in[0];
    const float* W = (const float*)d_in[1];
    if (n_in >= 2 && in_sizes[0] == Dn * Mn * On * In) {
        x = (const float*)d_in[1];
        W = (const float*)d_in[0];
    }
    float* out = (float*)d_out;

    transpose_W_kernel<<<(Dn * On * 2 * Mn + 255) / 256, 256>>>(W);

    size_t smem = SMEM_FLOATS * sizeof(float);
    cudaFuncSetAttribute(caps_routing_kernel,
                         cudaFuncAttributeMaxDynamicSharedMemorySize, (int)smem);
    caps_routing_kernel<<<Bn, THREADS, smem>>>(x, out);
}

// round 6
// speedup vs baseline: 1.2445x; 1.2445x over previous
#include <cuda_runtime.h>
#include <math.h>

// Problem constants
#define Bn 256
#define Dn 10
#define Mn 32
#define Pn 36
#define In 8
#define On 16

#define THREADS 320            // 10 warps: warp = d, lane = m

// x smem row stride (P*I=288 + 4 pad) -> conflict-free LDS.128
#define XROW 292
#define XS_FLOATS (Mn * XROW)           // 9344
#define WVS_FLOATS (Dn * Mn * In)       // 2560
#define CSROW 37                        // float2 row stride for stats (pad)
#define CS_FLOAT2S (Mn * CSROW)         // 1184
#define SMEM_FLOATS (XS_FLOATS + WVS_FLOATS + 2 * CS_FLOAT2S)   // 14272 -> 57088 B

// Transposed W: Wt[d][o][ih][m] as float4 -> coalesced LDG.128 over lane m
__device__ float4 Wt_g[Dn * On * 2 * Mn];

__global__ void transpose_W_kernel(const float* __restrict__ W) {
    int idx = blockIdx.x * blockDim.x + threadIdx.x;
    if (idx >= Dn * On * 2 * Mn) return;
    int m  = idx & 31;
    int r  = idx >> 5;
    int ih = r & 1;  r >>= 1;
    int o  = r & 15;
    int d  = r >> 4;
    const float4* Wsrc = (const float4*)W;
    Wt_g[idx] = Wsrc[((d * Mn + m) * On + o) * 2 + ih];
}

// Distributed compute_v: per-lane partials, decimated lane reduction (16 shfl),
// squash. Returns s[o]*k on lanes 2o and 2o+1 (o = m>>1).
__device__ __forceinline__ float compute_v_dist(int d, int m, const float xc[In]) {
    const float4* Wt = Wt_g + (d * On * 2) * Mn + m;
    float v[On];
#pragma unroll
    for (int o = 0; o < On; o++) {
        float4 w0 = __ldg(Wt + (2 * o) * Mn);
        float4 w1 = __ldg(Wt + (2 * o + 1) * Mn);
        v[o] = w0.x * xc[0] + w0.y * xc[1] + w0.z * xc[2] + w0.w * xc[3]
             + w1.x * xc[4] + w1.y * xc[5] + w1.z * xc[6] + w1.w * xc[7];
    }
    bool h = (m & 16);
    float a8[8];
#pragma unroll
    for (int j = 0; j < 8; j++) {
        float send = h ? v[j] : v[j + 8];
        float keep = h ? v[j + 8] : v[j];
        a8[j] = keep + __shfl_xor_sync(0xffffffffu, send, 16);
    }
    h = (m & 8);
    float a4[4];
#pragma unroll
    for (int j = 0; j < 4; j++) {
        float send = h ? a8[j] : a8[j + 4];
        float keep = h ? a8[j + 4] : a8[j];
        a4[j] = keep + __shfl_xor_sync(0xffffffffu, send, 8);
    }
    h = (m & 4);
    float a2[2];
#pragma unroll
    for (int j = 0; j < 2; j++) {
        float send = h ? a4[j] : a4[j + 2];
        float keep = h ? a4[j + 2] : a4[j];
        a2[j] = keep + __shfl_xor_sync(0xffffffffu, send, 4);
    }
    h = (m & 2);
    float send = h ? a2[0] : a2[1];
    float keep = h ? a2[1] : a2[0];
    float s1 = keep + __shfl_xor_sync(0xffffffffu, send, 2);
    s1 += __shfl_xor_sync(0xffffffffu, s1, 1);

    float sq = s1 * s1;
    sq += __shfl_xor_sync(0xffffffffu, sq, 2);
    sq += __shfl_xor_sync(0xffffffffu, sq, 4);
    sq += __shfl_xor_sync(0xffffffffu, sq, 8);
    sq += __shfl_xor_sync(0xffffffffu, sq, 16);
    float k = __fdividef(sq, 1.0f + sq) * rsqrtf(sq + 1e-7f);
    return s1 * k;
}

__device__ __forceinline__ void bcast_v(float vd, float vo[On]) {
#pragma unroll
    for (int o = 0; o < On; o++)
        vo[o] = __shfl_sync(0xffffffffu, vd, 2 * o);
}

__device__ __forceinline__ void compute_wv(int d, int m, const float vo[On], float wv[In]) {
    const float4* Wt = Wt_g + (d * On * 2) * Mn + m;
#pragma unroll
    for (int i = 0; i < In; i++) wv[i] = 0.f;
#pragma unroll
    for (int o = 0; o < On; o++) {
        float4 w0 = __ldg(Wt + (2 * o) * Mn);
        float4 w1 = __ldg(Wt + (2 * o + 1) * Mn);
        float v = vo[o];
        wv[0] += w0.x * v; wv[1] += w0.y * v; wv[2] += w0.z * v; wv[3] += w0.w * v;
        wv[4] += w1.x * v; wv[5] += w1.y * v; wv[6] += w1.z * v; wv[7] += w1.w * v;
    }
}

__device__ __forceinline__ float dot8(const float4 a, const float4 q, const float w[In]) {
    return a.x * w[0] + a.y * w[1] + a.z * w[2] + a.w * w[3]
         + q.x * w[4] + q.y * w[5] + q.z * w[6] + q.w * w[7];
}

__global__ __launch_bounds__(THREADS, 2)
void caps_routing_kernel(const float* __restrict__ x,
                         float* __restrict__ out) {
    extern __shared__ float sm[];
    float*  xs   = sm;                          // [Mn][XROW]
    float*  wvs  = xs + XS_FLOATS;              // [Dn*Mn][8]
    float2* cs   = (float2*)(wvs + WVS_FLOATS); // [Mn][CSROW] (mx, rs)
    float*  xsum = (float*)cs;                  // early overlap: [Mn][9]

    const int bidx = blockIdx.x;
    const int tid  = threadIdx.x;
    const int d    = tid >> 5;
    const int m    = tid & 31;

    // ---- load x[bidx] into padded smem (coalesced float4) ----
    {
        const float4* xg = (const float4*)(x + (size_t)bidx * (Mn * Pn * In));
        const int row4 = (Pn * In) / 4;   // 72
        for (int idx = tid; idx < Mn * row4; idx += THREADS) {
            int mm = idx / row4;
            int j  = idx - mm * row4;
            ((float4*)(xs + mm * XROW))[j] = xg[idx];
        }
    }
    __syncthreads();

    // ---- cooperative xsum[m][i] = (1/D) * sum_p x[m,p,i] ----
    if (tid < Mn * In) {
        int mm = tid >> 3, ii = tid & 7;
        const float* xr = xs + mm * XROW + ii;
        float s = 0.f;
#pragma unroll 6
        for (int p = 0; p < Pn; p++) s += xr[8 * p];
        xsum[mm * 9 + ii] = s * (1.0f / Dn);
    }
    __syncthreads();

    const float4* xm = (const float4*)(xs + m * XROW);

    float xc[In], wv1[In], wv2[In], vo[On];

    // ================= iteration 1: c = 1/D =================
#pragma unroll
    for (int i = 0; i < In; i++) xc[i] = xsum[m * 9 + i];

    float vd = compute_v_dist(d, m, xc);
    bcast_v(vd, vo);
    compute_wv(d, m, vo, wv1);

    // publish wv1 for cross-d softmax stats
    {
        float4* w4 = (float4*)(wvs + (d * Mn + m) * In);
        w4[0] = make_float4(wv1[0], wv1[1], wv1[2], wv1[3]);
        w4[1] = make_float4(wv1[4], wv1[5], wv1[6], wv1[7]);
    }
    __syncthreads();

    // ===== axis-1 (d) softmax stats per (m,p): b[d] = x_p . wv1[d,m] =====
    for (int col = tid; col < Mn * Pn; col += THREADS) {
        int cm = col / Pn, cp = col - cm * Pn;
        float4 xa = *(const float4*)(xs + cm * XROW + 8 * cp);
        float4 xq = *(const float4*)(xs + cm * XROW + 8 * cp + 4);
        float bv[Dn];
        float vmax = -1e30f;
#pragma unroll
        for (int dd = 0; dd < Dn; dd++) {
            const float4* w4 = (const float4*)(wvs + (dd * Mn + cm) * In);
            float4 wa = w4[0], wb = w4[1];
            float b = xa.x * wa.x + xa.y * wa.y + xa.z * wa.z + xa.w * wa.w
                    + xq.x * wb.x + xq.y * wb.y + xq.z * wb.z + xq.w * wb.w;
            bv[dd] = b;
            vmax = fmaxf(vmax, b);
        }
        float ssum = 0.f;
#pragma unroll
        for (int dd = 0; dd < Dn; dd++) ssum += __expf(bv[dd] - vmax);
        cs[cm * CSROW + cp] = make_float2(vmax, __fdividef(1.0f, ssum));
    }
    __syncthreads();

    // ===== iteration 2 (b recomputed on the fly) — dual accumulator sets =====
    {
        const float2* csr = cs + m * CSROW;
        float xa8[In], xb8[In];
#pragma unroll
        for (int i = 0; i < In; i++) { xa8[i] = 0.f; xb8[i] = 0.f; }
#pragma unroll 6
        for (int p = 0; p < Pn; p += 2) {
            // even p -> set A
            {
                float4 a = xm[2 * p], q = xm[2 * p + 1];
                float2 st = csr[p];
                float c = __expf(dot8(a, q, wv1) - st.x) * st.y;
                xa8[0] += c * a.x; xa8[1] += c * a.y; xa8[2] += c * a.z; xa8[3] += c * a.w;
                xa8[4] += c * q.x; xa8[5] += c * q.y; xa8[6] += c * q.z; xa8[7] += c * q.w;
            }
            // odd p -> set B
            {
                float4 a = xm[2 * p + 2], q = xm[2 * p + 3];
                float2 st = csr[p + 1];
                float c = __expf(dot8(a, q, wv1) - st.x) * st.y;
                xb8[0] += c * a.x; xb8[1] += c * a.y; xb8[2] += c * a.z; xb8[3] += c * a.w;
                xb8[4] += c * q.x; xb8[5] += c * q.y; xb8[6] += c * q.z; xb8[7] += c * q.w;
            }
        }
#pragma unroll
        for (int i = 0; i < In; i++) xc[i] = xa8[i] + xb8[i];
    }
    vd = compute_v_dist(d, m, xc);
    bcast_v(vd, vo);
    compute_wv(d, m, vo, wv2);

    // b_final(p) = x_p . (wv1 + wv2)
    float wvt[In];
#pragma unroll
    for (int i = 0; i < In; i++) wvt[i] = wv1[i] + wv2[i];

    // ===== FUSED final: axis-3 softmax (online, TWO independent states) =====
    {
        float M0 = -1e30f, Z0 = 0.f, M1 = -1e30f, Z1 = 0.f;
        float acc0[In], acc1[In];
#pragma unroll
        for (int i = 0; i < In; i++) { acc0[i] = 0.f; acc1[i] = 0.f; }
#pragma unroll 6
        for (int p = 0; p < Pn; p += 2) {
            {   // even p -> state 0
                float4 a = xm[2 * p], q = xm[2 * p + 1];
                float b = dot8(a, q, wvt);
                float M2 = fmaxf(M0, b);
                float sc = __expf(M0 - M2);
                float w = __expf(b - M2);
                Z0 = Z0 * sc + w;
                acc0[0] = acc0[0] * sc + w * a.x;
                acc0[1] = acc0[1] * sc + w * a.y;
                acc0[2] = acc0[2] * sc + w * a.z;
                acc0[3] = acc0[3] * sc + w * a.w;
                acc0[4] = acc0[4] * sc + w * q.x;
                acc0[5] = acc0[5] * sc + w * q.y;
                acc0[6] = acc0[6] * sc + w * q.z;
                acc0[7] = acc0[7] * sc + w * q.w;
                M0 = M2;
            }
            {   // odd p -> state 1
                float4 a = xm[2 * p + 2], q = xm[2 * p + 3];
                float b = dot8(a, q, wvt);
                float M2 = fmaxf(M1, b);
                float sc = __expf(M1 - M2);
                float w = __expf(b - M2);
                Z1 = Z1 * sc + w;
                acc1[0] = acc1[0] * sc + w * a.x;
                acc1[1] = acc1[1] * sc + w * a.y;
                acc1[2] = acc1[2] * sc + w * a.z;
                acc1[3] = acc1[3] * sc + w * a.w;
                acc1[4] = acc1[4] * sc + w * q.x;
                acc1[5] = acc1[5] * sc + w * q.y;
                acc1[6] = acc1[6] * sc + w * q.z;
                acc1[7] = acc1[7] * sc + w * q.w;
                M1 = M2;
            }
        }
        // combine the two online states
        float Mg = fmaxf(M0, M1);
        float f0 = __expf(M0 - Mg), f1 = __expf(M1 - Mg);
        float Z = Z0 * f0 + Z1 * f1;
        float rz = __fdividef(1.0f, Z);
#pragma unroll
        for (int i = 0; i < In; i++)
            xc[i] = (acc0[i] * f0 + acc1[i] * f1) * rz;
    }
    vd = compute_v_dist(d, m, xc);

    if (!(m & 1))
        out[((size_t)bidx * Dn + d) * On + (m >> 1)] = vd;
}

extern "C" void kernel_launch(void* const* d_in, const int* in_sizes, int n_in,
                              void* d_out, int out_size) {
    const float* x = (const float*)d_in[0];
    const float* W = (const float*)d_in[1];
    if (n_in >= 2 && in_sizes[0] == Dn * Mn * On * In) {
        x = (const float*)d_in[1];
        W = (const float*)d_in[0];
    }
    float* out = (float*)d_out;

    transpose_W_kernel<<<(Dn * On * 2 * Mn + 255) / 256, 256>>>(W);

    size_t smem = SMEM_FLOATS * sizeof(float);
    cudaFuncSetAttribute(caps_routing_kernel,
                         cudaFuncAttributeMaxDynamicSharedMemorySize, (int)smem);
    caps_routing_kernel<<<Bn, THREADS, smem>>>(x, out);
}

// round 7
// speedup vs baseline: 1.3255x; 1.0651x over previous
#include <cuda_runtime.h>
#include <math.h>

// Problem constants
#define Bn 256
#define Dn 10
#define Mn 32
#define Pn 36
#define In 8
#define On 16

#define THREADS 320            // 10 warps: warp = d, lane = m

// x smem row stride (P*I=288 + 4 pad) -> conflict-free LDS.128
#define XROW 292
#define XS_FLOATS (Mn * XROW)           // 9344
#define WVS_FLOATS (Dn * Mn * In)       // 2560
#define CSROW 37                        // float row stride for stats (pad)
#define CS_FLOATS (Mn * CSROW)          // 1184
#define SMEM_FLOATS (XS_FLOATS + WVS_FLOATS + CS_FLOATS)   // 13088 -> 52352 B

// Transposed W: Wt[d][o][ih][m] as float4 -> coalesced LDG.128 over lane m
__device__ float4 Wt_g[Dn * On * 2 * Mn];

__global__ void transpose_W_kernel(const float* __restrict__ W) {
    int idx = blockIdx.x * blockDim.x + threadIdx.x;
    if (idx >= Dn * On * 2 * Mn) return;
    int m  = idx & 31;
    int r  = idx >> 5;
    int ih = r & 1;  r >>= 1;
    int o  = r & 15;
    int d  = r >> 4;
    const float4* Wsrc = (const float4*)W;
    Wt_g[idx] = Wsrc[((d * Mn + m) * On + o) * 2 + ih];
}

// Distributed compute_v: per-lane partials, decimated lane reduction (16 shfl),
// squash. Returns s[o]*k on lanes 2o and 2o+1 (o = m>>1).
__device__ __forceinline__ float compute_v_dist(int d, int m, const float xc[In]) {
    const float4* Wt = Wt_g + (d * On * 2) * Mn + m;
    float v[On];
#pragma unroll
    for (int o = 0; o < On; o++) {
        float4 w0 = __ldg(Wt + (2 * o) * Mn);
        float4 w1 = __ldg(Wt + (2 * o + 1) * Mn);
        v[o] = w0.x * xc[0] + w0.y * xc[1] + w0.z * xc[2] + w0.w * xc[3]
             + w1.x * xc[4] + w1.y * xc[5] + w1.z * xc[6] + w1.w * xc[7];
    }
    bool h = (m & 16);
    float a8[8];
#pragma unroll
    for (int j = 0; j < 8; j++) {
        float send = h ? v[j] : v[j + 8];
        float keep = h ? v[j + 8] : v[j];
        a8[j] = keep + __shfl_xor_sync(0xffffffffu, send, 16);
    }
    h = (m & 8);
    float a4[4];
#pragma unroll
    for (int j = 0; j < 4; j++) {
        float send = h ? a8[j] : a8[j + 4];
        float keep = h ? a8[j + 4] : a8[j];
        a4[j] = keep + __shfl_xor_sync(0xffffffffu, send, 8);
    }
    h = (m & 4);
    float a2[2];
#pragma unroll
    for (int j = 0; j < 2; j++) {
        float send = h ? a4[j] : a4[j + 2];
        float keep = h ? a4[j + 2] : a4[j];
        a2[j] = keep + __shfl_xor_sync(0xffffffffu, send, 4);
    }
    h = (m & 2);
    float send = h ? a2[0] : a2[1];
    float keep = h ? a2[1] : a2[0];
    float s1 = keep + __shfl_xor_sync(0xffffffffu, send, 2);
    s1 += __shfl_xor_sync(0xffffffffu, s1, 1);

    float sq = s1 * s1;
    sq += __shfl_xor_sync(0xffffffffu, sq, 2);
    sq += __shfl_xor_sync(0xffffffffu, sq, 4);
    sq += __shfl_xor_sync(0xffffffffu, sq, 8);
    sq += __shfl_xor_sync(0xffffffffu, sq, 16);
    float k = __fdividef(sq, 1.0f + sq) * rsqrtf(sq + 1e-7f);
    return s1 * k;
}

__device__ __forceinline__ void bcast_v(float vd, float vo[On]) {
#pragma unroll
    for (int o = 0; o < On; o++)
        vo[o] = __shfl_sync(0xffffffffu, vd, 2 * o);
}

__device__ __forceinline__ void compute_wv(int d, int m, const float vo[On], float wv[In]) {
    const float4* Wt = Wt_g + (d * On * 2) * Mn + m;
#pragma unroll
    for (int i = 0; i < In; i++) wv[i] = 0.f;
#pragma unroll
    for (int o = 0; o < On; o++) {
        float4 w0 = __ldg(Wt + (2 * o) * Mn);
        float4 w1 = __ldg(Wt + (2 * o + 1) * Mn);
        float v = vo[o];
        wv[0] += w0.x * v; wv[1] += w0.y * v; wv[2] += w0.z * v; wv[3] += w0.w * v;
        wv[4] += w1.x * v; wv[5] += w1.y * v; wv[6] += w1.z * v; wv[7] += w1.w * v;
    }
}

__device__ __forceinline__ float dot8(const float4 a, const float4 q, const float w[In]) {
    return a.x * w[0] + a.y * w[1] + a.z * w[2] + a.w * w[3]
         + q.x * w[4] + q.y * w[5] + q.z * w[6] + q.w * w[7];
}

__global__ __launch_bounds__(THREADS, 2)
void caps_routing_kernel(const float* __restrict__ x,
                         float* __restrict__ out) {
    extern __shared__ float sm[];
    float*  xs   = sm;                          // [Mn][XROW]
    float*  wvs  = xs + XS_FLOATS;              // [Dn*Mn][8]
    float*  cs   = wvs + WVS_FLOATS;            // [Mn][CSROW] (rs only)
    float*  xsum = cs;                          // early overlap: [Mn][9]

    const int bidx = blockIdx.x;
    const int tid  = threadIdx.x;
    const int d    = tid >> 5;
    const int m    = tid & 31;

    // ---- load x[bidx] into padded smem (coalesced float4) ----
    {
        const float4* xg = (const float4*)(x + (size_t)bidx * (Mn * Pn * In));
        const int row4 = (Pn * In) / 4;   // 72
        for (int idx = tid; idx < Mn * row4; idx += THREADS) {
            int mm = idx / row4;
            int j  = idx - mm * row4;
            ((float4*)(xs + mm * XROW))[j] = xg[idx];
        }
    }
    __syncthreads();

    // ---- cooperative xsum[m][i] = (1/D) * sum_p x[m,p,i] ----
    if (tid < Mn * In) {
        int mm = tid >> 3, ii = tid & 7;
        const float* xr = xs + mm * XROW + ii;
        float s = 0.f;
#pragma unroll
        for (int p = 0; p < Pn; p++) s += xr[8 * p];
        xsum[mm * 9 + ii] = s * (1.0f / Dn);
    }
    __syncthreads();

    const float4* xm = (const float4*)(xs + m * XROW);

    float xc[In], wv1[In], wv2[In], vo[On];

    // ================= iteration 1: c = 1/D =================
#pragma unroll
    for (int i = 0; i < In; i++) xc[i] = xsum[m * 9 + i];

    float vd = compute_v_dist(d, m, xc);
    bcast_v(vd, vo);
    compute_wv(d, m, vo, wv1);

    // publish wv1 for cross-d softmax stats
    {
        float4* w4 = (float4*)(wvs + (d * Mn + m) * In);
        w4[0] = make_float4(wv1[0], wv1[1], wv1[2], wv1[3]);
        w4[1] = make_float4(wv1[4], wv1[5], wv1[6], wv1[7]);
    }
    __syncthreads();

    // ===== axis-1 (d) softmax stats per (m,p): b[d] = x_p . wv1[d,m] =====
    // |b| is tightly bounded (squash => ||v||<1, W ~ 0.01) so exp needs no
    // max subtraction; store only rs = 1/sum(exp(b)).
    for (int col = tid; col < Mn * Pn; col += THREADS) {
        int cm = col / Pn, cp = col - cm * Pn;
        float4 xa = *(const float4*)(xs + cm * XROW + 8 * cp);
        float4 xq = *(const float4*)(xs + cm * XROW + 8 * cp + 4);
        float ssum = 0.f;
#pragma unroll
        for (int dd = 0; dd < Dn; dd++) {
            const float4* w4 = (const float4*)(wvs + (dd * Mn + cm) * In);
            float4 wa = w4[0], wb = w4[1];
            float b = xa.x * wa.x + xa.y * wa.y + xa.z * wa.z + xa.w * wa.w
                    + xq.x * wb.x + xq.y * wb.y + xq.z * wb.z + xq.w * wb.w;
            ssum += __expf(b);
        }
        cs[cm * CSROW + cp] = __fdividef(1.0f, ssum);
    }
    __syncthreads();

    // ================= iteration 2 (b recomputed on the fly) =================
    {
        const float* rsr = cs + m * CSROW;
#pragma unroll
        for (int i = 0; i < In; i++) xc[i] = 0.f;
        for (int p = 0; p < Pn; p++) {
            float4 a = xm[2 * p], q = xm[2 * p + 1];
            float c = __expf(dot8(a, q, wv1)) * rsr[p];
            xc[0] += c * a.x; xc[1] += c * a.y; xc[2] += c * a.z; xc[3] += c * a.w;
            xc[4] += c * q.x; xc[5] += c * q.y; xc[6] += c * q.z; xc[7] += c * q.w;
        }
    }
    vd = compute_v_dist(d, m, xc);
    bcast_v(vd, vo);
    compute_wv(d, m, vo, wv2);

    // b_final(p) = x_p . (wv1 + wv2)
    float wvt[In];
#pragma unroll
    for (int i = 0; i < In; i++) wvt[i] = wv1[i] + wv2[i];

    // ===== FUSED final: axis-3 softmax (no max needed) + weighted x acc =====
    {
        float Z = 0.f;
        float acc[In];
#pragma unroll
        for (int i = 0; i < In; i++) acc[i] = 0.f;
        for (int p = 0; p < Pn; p++) {
            float4 a = xm[2 * p], q = xm[2 * p + 1];
            float w = __expf(dot8(a, q, wvt));
            Z += w;
            acc[0] += w * a.x;
            acc[1] += w * a.y;
            acc[2] += w * a.z;
            acc[3] += w * a.w;
            acc[4] += w * q.x;
            acc[5] += w * q.y;
            acc[6] += w * q.z;
            acc[7] += w * q.w;
        }
        float rz = __fdividef(1.0f, Z);
#pragma unroll
        for (int i = 0; i < In; i++) xc[i] = acc[i] * rz;
    }
    vd = compute_v_dist(d, m, xc);

    if (!(m & 1))
        out[((size_t)bidx * Dn + d) * On + (m >> 1)] = vd;
}

extern "C" void kernel_launch(void* const* d_in, const int* in_sizes, int n_in,
                              void* d_out, int out_size) {
    const float* x = (const float*)d_in[0];
    const float* W = (const float*)d_in[1];
    if (n_in >= 2 && in_sizes[0] == Dn * Mn * On * In) {
        x = (const float*)d_in[1];
        W = (const float*)d_in[0];
    }
    float* out = (float*)d_out;

    transpose_W_kernel<<<(Dn * On * 2 * Mn + 255) / 256, 256>>>(W);

    size_t smem = SMEM_FLOATS * sizeof(float);
    cudaFuncSetAttribute(caps_routing_kernel,
                         cudaFuncAttributeMaxDynamicSharedMemorySize, (int)smem);
    caps_routing_kernel<<<Bn, THREADS, smem>>>(x, out);
}

// round 8
// speedup vs baseline: 1.4303x; 1.0790x over previous
#include <cuda_runtime.h>
#include <math.h>

// Problem constants
#define Bn 256
#define Dn 10
#define Mn 32
#define Pn 36
#define In 8
#define On 16

#define THREADS 320            // 10 warps: warp = d, lane = m

// x smem row stride (P*I=288 + 4 pad) -> conflict-free LDS.128
#define XROW 292
#define XS_FLOATS (Mn * XROW)           // 9344
#define WVS_FLOATS (Dn * Mn * In)       // 2560
#define CSROW 37                        // float2 row stride for stats (pad)
#define CS_FLOAT2S (Mn * CSROW)         // 1184
#define SMEM_FLOATS (XS_FLOATS + WVS_FLOATS + 2 * CS_FLOAT2S)   // 14272 -> 57088 B

typedef unsigned long long u64;

// ---- packed f32x2 helpers (sm_103a dual-lane fp32; PTX-only) ----
__device__ __forceinline__ u64 pk2(float lo, float hi) {
    u64 r; asm("mov.b64 %0, {%1, %2};" : "=l"(r) : "f"(lo), "f"(hi)); return r;
}
__device__ __forceinline__ void upk2(u64 v, float& a, float& b) {
    asm("mov.b64 {%0, %1}, %2;" : "=f"(a), "=f"(b) : "l"(v));
}
__device__ __forceinline__ u64 fma2_(u64 a, u64 b, u64 c) {
    u64 d; asm("fma.rn.f32x2 %0, %1, %2, %3;" : "=l"(d) : "l"(a), "l"(b), "l"(c)); return d;
}
__device__ __forceinline__ u64 mul2_(u64 a, u64 b) {
    u64 d; asm("mul.rn.f32x2 %0, %1, %2;" : "=l"(d) : "l"(a), "l"(b)); return d;
}
__device__ __forceinline__ u64 add2_(u64 a, u64 b) {
    u64 d; asm("add.rn.f32x2 %0, %1, %2;" : "=l"(d) : "l"(a), "l"(b)); return d;
}

// Transposed W: Wt[d][o][ih][m] as float4 -> coalesced LDG.128 over lane m
__device__ float4 Wt_g[Dn * On * 2 * Mn];

__global__ void transpose_W_kernel(const float* __restrict__ W) {
    int idx = blockIdx.x * blockDim.x + threadIdx.x;
    if (idx >= Dn * On * 2 * Mn) return;
    int m  = idx & 31;
    int r  = idx >> 5;
    int ih = r & 1;  r >>= 1;
    int o  = r & 15;
    int d  = r >> 4;
    const float4* Wsrc = (const float4*)W;
    Wt_g[idx] = Wsrc[((d * Mn + m) * On + o) * 2 + ih];
}

// Distributed compute_v: per-lane partials (packed FMA), decimated lane
// reduction, squash. xc is 4 packed pairs. Returns s[o]*k on lanes 2o,2o+1.
__device__ __forceinline__ float compute_v_dist(int d, int m, const u64 xc[4]) {
    const ulonglong2* Wt = (const ulonglong2*)(Wt_g + (d * On * 2) * Mn + m);
    float v[On];
#pragma unroll
    for (int o = 0; o < On; o++) {
        ulonglong2 Wa = __ldg(Wt + (size_t)(2 * o) * Mn);
        ulonglong2 Wb = __ldg(Wt + (size_t)(2 * o + 1) * Mn);
        u64 t = mul2_(Wa.x, xc[0]);
        t = fma2_(Wa.y, xc[1], t);
        t = fma2_(Wb.x, xc[2], t);
        t = fma2_(Wb.y, xc[3], t);
        float tl, th; upk2(t, tl, th);
        v[o] = tl + th;
    }
    bool h = (m & 16);
    float a8[8];
#pragma unroll
    for (int j = 0; j < 8; j++) {
        float send = h ? v[j] : v[j + 8];
        float keep = h ? v[j + 8] : v[j];
        a8[j] = keep + __shfl_xor_sync(0xffffffffu, send, 16);
    }
    h = (m & 8);
    float a4[4];
#pragma unroll
    for (int j = 0; j < 4; j++) {
        float send = h ? a8[j] : a8[j + 4];
        float keep = h ? a8[j + 4] : a8[j];
        a4[j] = keep + __shfl_xor_sync(0xffffffffu, send, 8);
    }
    h = (m & 4);
    float a2[2];
#pragma unroll
    for (int j = 0; j < 2; j++) {
        float send = h ? a4[j] : a4[j + 2];
        float keep = h ? a4[j + 2] : a4[j];
        a2[j] = keep + __shfl_xor_sync(0xffffffffu, send, 4);
    }
    h = (m & 2);
    float send = h ? a2[0] : a2[1];
    float keep = h ? a2[1] : a2[0];
    float s1 = keep + __shfl_xor_sync(0xffffffffu, send, 2);
    s1 += __shfl_xor_sync(0xffffffffu, s1, 1);

    float sq = s1 * s1;
    sq += __shfl_xor_sync(0xffffffffu, sq, 2);
    sq += __shfl_xor_sync(0xffffffffu, sq, 4);
    sq += __shfl_xor_sync(0xffffffffu, sq, 8);
    sq += __shfl_xor_sync(0xffffffffu, sq, 16);
    float k = sq / ((1.0f + sq) * sqrtf(sq + 1e-7f));
    return s1 * k;
}

__device__ __forceinline__ void bcast_v(float vd, float vo[On]) {
#pragma unroll
    for (int o = 0; o < On; o++)
        vo[o] = __shfl_sync(0xffffffffu, vd, 2 * o);
}

// wv (4 packed pairs) = sum_o W[d,m,o,:] * v[o]  — packed vertical FMA
__device__ __forceinline__ void compute_wv(int d, int m, const float vo[On], u64 wv[4]) {
    const ulonglong2* Wt = (const ulonglong2*)(Wt_g + (d * On * 2) * Mn + m);
    wv[0] = 0ull; wv[1] = 0ull; wv[2] = 0ull; wv[3] = 0ull;
#pragma unroll
    for (int o = 0; o < On; o++) {
        ulonglong2 Wa = __ldg(Wt + (size_t)(2 * o) * Mn);
        ulonglong2 Wb = __ldg(Wt + (size_t)(2 * o + 1) * Mn);
        u64 vv = pk2(vo[o], vo[o]);
        wv[0] = fma2_(Wa.x, vv, wv[0]);
        wv[1] = fma2_(Wa.y, vv, wv[1]);
        wv[2] = fma2_(Wb.x, vv, wv[2]);
        wv[3] = fma2_(Wb.y, vv, wv[3]);
    }
}

// packed dot of x pair-quad with packed weight pairs -> scalar
__device__ __forceinline__ float dot8p(const ulonglong2 xa, const ulonglong2 xq,
                                       const u64 w[4]) {
    u64 t = mul2_(xa.x, w[0]);
    t = fma2_(xa.y, w[1], t);
    t = fma2_(xq.x, w[2], t);
    t = fma2_(xq.y, w[3], t);
    float tl, th; upk2(t, tl, th);
    return tl + th;
}

__global__ __launch_bounds__(THREADS, 2)
void caps_routing_kernel(const float* __restrict__ x,
                         float* __restrict__ out) {
    extern __shared__ float sm[];
    float*  xs   = sm;                          // [Mn][XROW]
    float*  wvs  = xs + XS_FLOATS;              // [Dn*Mn][8]
    float2* cs   = (float2*)(wvs + WVS_FLOATS); // [Mn][CSROW] (mx, rs)
    float*  xsum = (float*)cs;                  // early overlap: [Mn][10]

    const int bidx = blockIdx.x;
    const int tid  = threadIdx.x;
    const int d    = tid >> 5;
    const int m    = tid & 31;

    // ---- load x[bidx] into padded smem (coalesced float4) ----
    {
        const float4* xg = (const float4*)(x + (size_t)bidx * (Mn * Pn * In));
        const int row4 = (Pn * In) / 4;   // 72
        for (int idx = tid; idx < Mn * row4; idx += THREADS) {
            int mm = idx / row4;
            int j  = idx - mm * row4;
            ((float4*)(xs + mm * XROW))[j] = xg[idx];
        }
    }
    __syncthreads();

    // ---- cooperative xsum[m][i] = (1/D) * sum_p x[m,p,i] (stride 10, 8B-aligned) ----
    if (tid < Mn * In) {
        int mm = tid >> 3, ii = tid & 7;
        const float* xr = xs + mm * XROW + ii;
        float s = 0.f;
#pragma unroll
        for (int p = 0; p < Pn; p++) s += xr[8 * p];
        xsum[mm * 10 + ii] = s * (1.0f / Dn);
    }
    __syncthreads();

    const ulonglong2* xm = (const ulonglong2*)(xs + m * XROW);

    u64 xc[4], wv1[4], wv2[4];
    float vo[On];

    // ================= iteration 1: c = 1/D =================
#pragma unroll
    for (int j = 0; j < 4; j++)
        xc[j] = *(const u64*)(xsum + m * 10 + 2 * j);

    float vd = compute_v_dist(d, m, xc);
    bcast_v(vd, vo);
    compute_wv(d, m, vo, wv1);

    // publish wv1 for cross-d softmax stats
    {
        u64* w8 = (u64*)(wvs + (d * Mn + m) * In);
        w8[0] = wv1[0]; w8[1] = wv1[1]; w8[2] = wv1[2]; w8[3] = wv1[3];
    }
    __syncthreads();

    // ===== axis-1 (d) softmax stats per (m,p): b[d] = x_p . wv1[d,m] =====
    for (int col = tid; col < Mn * Pn; col += THREADS) {
        int cm = col / Pn, cp = col - cm * Pn;
        ulonglong2 xa = *(const ulonglong2*)(xs + cm * XROW + 8 * cp);
        ulonglong2 xq = *(const ulonglong2*)(xs + cm * XROW + 8 * cp + 4);
        float bv[Dn];
        float vmax = -1e30f;
#pragma unroll
        for (int dd = 0; dd < Dn; dd++) {
            const u64* w8 = (const u64*)(wvs + (dd * Mn + cm) * In);
            u64 t = mul2_(xa.x, w8[0]);
            t = fma2_(xa.y, w8[1], t);
            t = fma2_(xq.x, w8[2], t);
            t = fma2_(xq.y, w8[3], t);
            float tl, th; upk2(t, tl, th);
            float b = tl + th;
            bv[dd] = b;
            vmax = fmaxf(vmax, b);
        }
        float ssum = 0.f;
#pragma unroll
        for (int dd = 0; dd < Dn; dd++) ssum += __expf(bv[dd] - vmax);
        cs[cm * CSROW + cp] = make_float2(vmax, 1.0f / ssum);
    }
    __syncthreads();

    // ================= iteration 2 (b recomputed on the fly) =================
    {
        const float2* csr = cs + m * CSROW;
        u64 acc[4] = {0ull, 0ull, 0ull, 0ull};
        for (int p = 0; p < Pn; p++) {
            ulonglong2 xa = xm[2 * p], xq = xm[2 * p + 1];
            float2 st = csr[p];
            float b = dot8p(xa, xq, wv1);
            float c = __expf(b - st.x) * st.y;
            u64 cc = pk2(c, c);
            acc[0] = fma2_(xa.x, cc, acc[0]);
            acc[1] = fma2_(xa.y, cc, acc[1]);
            acc[2] = fma2_(xq.x, cc, acc[2]);
            acc[3] = fma2_(xq.y, cc, acc[3]);
        }
        xc[0] = acc[0]; xc[1] = acc[1]; xc[2] = acc[2]; xc[3] = acc[3];
    }
    vd = compute_v_dist(d, m, xc);
    bcast_v(vd, vo);
    compute_wv(d, m, vo, wv2);

    // b_final(p) = x_p . (wv1 + wv2)
    u64 wvt[4];
#pragma unroll
    for (int j = 0; j < 4; j++) wvt[j] = add2_(wv1[j], wv2[j]);

    // ===== FUSED final: axis-3 softmax (online) + weighted x accumulation =====
    {
        float M = -1e30f, Z = 0.f;
        u64 acc[4] = {0ull, 0ull, 0ull, 0ull};
        for (int p = 0; p < Pn; p++) {
            ulonglong2 xa = xm[2 * p], xq = xm[2 * p + 1];
            float bnew = dot8p(xa, xq, wvt);
            float M2 = fmaxf(M, bnew);
            float scf = __expf(M - M2);
            float w = __expf(bnew - M2);
            Z = Z * scf + w;
            u64 sc2 = pk2(scf, scf);
            u64 w2 = pk2(w, w);
            acc[0] = fma2_(xa.x, w2, mul2_(acc[0], sc2));
            acc[1] = fma2_(xa.y, w2, mul2_(acc[1], sc2));
            acc[2] = fma2_(xq.x, w2, mul2_(acc[2], sc2));
            acc[3] = fma2_(xq.y, w2, mul2_(acc[3], sc2));
            M = M2;
        }
        float rz = 1.0f / Z;
        u64 rz2 = pk2(rz, rz);
#pragma unroll
        for (int j = 0; j < 4; j++) xc[j] = mul2_(acc[j], rz2);
    }
    vd = compute_v_dist(d, m, xc);

    if (!(m & 1))
        out[((size_t)bidx * Dn + d) * On + (m >> 1)] = vd;
}

extern "C" void kernel_launch(void* const* d_in, const int* in_sizes, int n_in,
                              void* d_out, int out_size) {
    const float* x = (const float*)d_in[0];
    const float* W = (const float*)d_in[1];
    if (n_in >= 2 && in_sizes[0] == Dn * Mn * On * In) {
        x = (const float*)d_in[1];
        W = (const float*)d_in[0];
    }
    float* out = (float*)d_out;

    transpose_W_kernel<<<(Dn * On * 2 * Mn + 255) / 256, 256>>>(W);

    size_t smem = SMEM_FLOATS * sizeof(float);
    cudaFuncSetAttribute(caps_routing_kernel,
                         cudaFuncAttributeMaxDynamicSharedMemorySize, (int)smem);
    caps_routing_kernel<<<Bn, THREADS, smem>>>(x, out);
}